// round 1
// baseline (speedup 1.0000x reference)
#include <cuda_runtime.h>

#define N0_   500000
#define N1_   100000
#define N2_   25000
#define E0_   1600000
#define E1_   400000
#define D_IN_ 128
#define D_H_  256
#define D_OUT_ 128

// ---- scratch (allocation-free rule: __device__ globals) ----
__device__ float g_agg0[(size_t)N1_ * D_IN_];   // 51.2 MB
__device__ float g_cnt0[N1_];
__device__ float g_h[(size_t)N1_ * D_H_];       // 102.4 MB
__device__ float g_agg1[(size_t)N2_ * D_H_];    // 25.6 MB
__device__ float g_cnt1[N2_];

// ---------------- utility kernels ----------------
__global__ void zero4(float4* __restrict__ p, int n4) {
    int i = blockIdx.x * blockDim.x + threadIdx.x;
    if (i < n4) p[i] = make_float4(0.f, 0.f, 0.f, 0.f);
}

__device__ __forceinline__ void red_add_v4(float* ptr, float4 v) {
    asm volatile("red.global.add.v4.f32 [%0], {%1,%2,%3,%4};"
                 :: "l"(ptr), "f"(v.x), "f"(v.y), "f"(v.z), "f"(v.w)
                 : "memory");
}

// one warp per edge; lane j handles float4 chunk(s) of the D-dim feature row
template<int D>
__global__ void scatter_edges(const float* __restrict__ feat,
                              const int* __restrict__ src,
                              const int* __restrict__ dst,
                              float* __restrict__ agg,
                              float* __restrict__ cnt, int nE) {
    int gw   = (blockIdx.x * blockDim.x + threadIdx.x) >> 5;
    int lane = threadIdx.x & 31;
    if (gw >= nE) return;
    int s = src[gw];
    int d = dst[gw];
    const float4* fs = (const float4*)(feat + (size_t)s * D);
    float* ag = agg + (size_t)d * D;
    #pragma unroll
    for (int j = 0; j < D / 128; j++) {
        float4 v = fs[j * 32 + lane];
        red_add_v4(ag + (size_t)(j * 32 + lane) * 4, v);
    }
    if (lane == 0) atomicAdd(&cnt[d], 1.0f);
}

// agg[row,:] *= 1/max(cnt[row],1)   (vectorized over float4 elements)
template<int D>
__global__ void meanify(float* __restrict__ agg, const float* __restrict__ cnt, int n) {
    int i = blockIdx.x * blockDim.x + threadIdx.x;   // over n * D/4
    int total = n * (D / 4);
    if (i >= total) return;
    int row = i / (D / 4);
    float inv = 1.0f / fmaxf(cnt[row], 1.0f);
    float4* p = (float4*)agg + i;
    float4 v = *p;
    v.x *= inv; v.y *= inv; v.z *= inv; v.w *= inv;
    *p = v;
}

// ---------------- fused dual-input SGEMM ----------------
// C[M,N] = opt_relu( A0[M,K0] @ B0[N,K0]^T + A1[M,K1] @ B1[N,K1]^T + bias[N] )
// Classic 128x128x8 register-tiled fp32 GEMM (256 threads, 8x8 per thread).
template<int K0, int K1, bool RELU>
__global__ void __launch_bounds__(256)
gemm_fused(const float* __restrict__ A0, const float* __restrict__ A1,
           const float* __restrict__ B0, const float* __restrict__ B1,
           const float* __restrict__ bias, float* __restrict__ C,
           int M, int N) {
    constexpr int K = K0 + K1;
    __shared__ float As[8][132];
    __shared__ float Bs[8][132];

    const int tid = threadIdx.x;
    const int bm = blockIdx.y * 128;
    const int bn = blockIdx.x * 128;

    // A-tile load mapping: thread -> (row 0..127, k4 0..1)
    const int arow = tid >> 1;
    const int acol = (tid & 1) * 4;
    // B-tile load mapping: thread -> (n 0..127, k4 0..1); B is [N,K] row-major
    const int bn_l = tid >> 1;
    const int bk   = (tid & 1) * 4;

    const int tr = (tid >> 4) * 8;   // 0..120
    const int tc = (tid & 15) * 8;   // 0..120

    float acc[8][8];
    #pragma unroll
    for (int i = 0; i < 8; i++)
        #pragma unroll
        for (int j = 0; j < 8; j++) acc[i][j] = 0.f;

    const int grow = bm + arow;
    const bool rowok = grow < M;
    const int gn = bn + bn_l;        // always < N (N multiple of 128)

    for (int kt = 0; kt < K; kt += 8) {
        // global loads
        float4 va = make_float4(0.f, 0.f, 0.f, 0.f);
        {
            int ka = kt + acol;
            if (rowok) {
                va = (ka < K0)
                   ? *(const float4*)(A0 + (size_t)grow * K0 + ka)
                   : *(const float4*)(A1 + (size_t)grow * K1 + (ka - K0));
            }
        }
        float4 vb;
        {
            int kb = kt + bk;
            vb = (kb < K0)
               ? *(const float4*)(B0 + (size_t)gn * K0 + kb)
               : *(const float4*)(B1 + (size_t)gn * K1 + (kb - K0));
        }
        __syncthreads();
        As[acol + 0][arow] = va.x;
        As[acol + 1][arow] = va.y;
        As[acol + 2][arow] = va.z;
        As[acol + 3][arow] = va.w;
        Bs[bk + 0][bn_l] = vb.x;
        Bs[bk + 1][bn_l] = vb.y;
        Bs[bk + 2][bn_l] = vb.z;
        Bs[bk + 3][bn_l] = vb.w;
        __syncthreads();

        #pragma unroll
        for (int kk = 0; kk < 8; kk++) {
            float ar[8], br[8];
            #pragma unroll
            for (int i = 0; i < 8; i++) ar[i] = As[kk][tr + i];
            #pragma unroll
            for (int j = 0; j < 8; j++) br[j] = Bs[kk][tc + j];
            #pragma unroll
            for (int i = 0; i < 8; i++)
                #pragma unroll
                for (int j = 0; j < 8; j++)
                    acc[i][j] = fmaf(ar[i], br[j], acc[i][j]);
        }
    }

    // epilogue: + bias, optional relu, vectorized store
    #pragma unroll
    for (int i = 0; i < 8; i++) {
        int r = bm + tr + i;
        if (r < M) {
            #pragma unroll
            for (int j = 0; j < 8; j += 4) {
                int c = bn + tc + j;
                float4 v;
                v.x = acc[i][j + 0] + bias[c + 0];
                v.y = acc[i][j + 1] + bias[c + 1];
                v.z = acc[i][j + 2] + bias[c + 2];
                v.w = acc[i][j + 3] + bias[c + 3];
                if (RELU) {
                    v.x = fmaxf(v.x, 0.f); v.y = fmaxf(v.y, 0.f);
                    v.z = fmaxf(v.z, 0.f); v.w = fmaxf(v.w, 0.f);
                }
                *(float4*)(C + (size_t)r * N + c) = v;
            }
        }
    }
}

// ---------------- host side ----------------
extern "C" void kernel_launch(void* const* d_in, const int* in_sizes, int n_in,
                              void* d_out, int out_size) {
    const float* x   = (const float*)d_in[0];
    const float* Wl0 = (const float*)d_in[1];
    const float* bl0 = (const float*)d_in[2];
    const float* Wr0 = (const float*)d_in[3];
    const float* Wl1 = (const float*)d_in[4];
    const float* bl1 = (const float*)d_in[5];
    const float* Wr1 = (const float*)d_in[6];
    const int* e0s = (const int*)d_in[7];
    const int* e0d = (const int*)d_in[8];
    const int* e1s = (const int*)d_in[9];
    const int* e1d = (const int*)d_in[10];
    float* out = (float*)d_out;

    float *agg0, *cnt0, *h, *agg1, *cnt1;
    cudaGetSymbolAddress((void**)&agg0, g_agg0);
    cudaGetSymbolAddress((void**)&cnt0, g_cnt0);
    cudaGetSymbolAddress((void**)&h,    g_h);
    cudaGetSymbolAddress((void**)&agg1, g_agg1);
    cudaGetSymbolAddress((void**)&cnt1, g_cnt1);

    // zero accumulators
    {
        int n4 = N1_ * D_IN_ / 4;
        zero4<<<(n4 + 255) / 256, 256>>>((float4*)agg0, n4);
        n4 = N1_ / 4;
        zero4<<<(n4 + 255) / 256, 256>>>((float4*)cnt0, n4);
        n4 = N2_ * D_H_ / 4;
        zero4<<<(n4 + 255) / 256, 256>>>((float4*)agg1, n4);
        n4 = N2_ / 4;
        zero4<<<(n4 + 255) / 256, 256>>>((float4*)cnt1, n4);
    }

    // hop 0: scatter x over edges -> agg0, then mean
    {
        long long thr = (long long)E0_ * 32;
        scatter_edges<D_IN_><<<(int)((thr + 255) / 256), 256>>>(x, e0s, e0d, agg0, cnt0, E0_);
        int t = N1_ * (D_IN_ / 4);
        meanify<D_IN_><<<(t + 255) / 256, 256>>>(agg0, cnt0, N1_);
    }

    // h = relu( mean_agg0 @ Wl0^T + x[:N1] @ Wr0^T + bl0 )   [N1, 256]
    {
        dim3 grid(D_H_ / 128, (N1_ + 127) / 128);
        gemm_fused<D_IN_, D_IN_, true><<<grid, 256>>>(agg0, x, Wl0, Wr0, bl0, h, N1_, D_H_);
    }

    // hop 1: scatter h over edges -> agg1, then mean
    {
        long long thr = (long long)E1_ * 32;
        scatter_edges<D_H_><<<(int)((thr + 255) / 256), 256>>>(h, e1s, e1d, agg1, cnt1, E1_);
        int t = N2_ * (D_H_ / 4);
        meanify<D_H_><<<(t + 255) / 256, 256>>>(agg1, cnt1, N2_);
    }

    // out = mean_agg1 @ Wl1^T + h[:N2] @ Wr1^T + bl1   [N2, 128]
    {
        dim3 grid(D_OUT_ / 128, (N2_ + 127) / 128);
        gemm_fused<D_H_, D_H_, false><<<grid, 256>>>(agg1, h, Wl1, Wr1, bl1, out, N2_, D_OUT_);
    }
}

// round 3
// speedup vs baseline: 1.4257x; 1.4257x over previous
#include <cuda_runtime.h>
#include <cuda_bf16.h>
#include <cstdint>

#define N0_   500000
#define N1_   100000
#define N2_   25000
#define E0_   1600000
#define E1_   400000
#define D_IN_ 128
#define D_H_  256
#define D_OUT_ 128

// ---- scratch (allocation-free rule: __device__ globals) ----
__device__ float g_agg0[(size_t)N1_ * D_IN_];
__device__ float g_cnt0[N1_];
__device__ float g_h[(size_t)N1_ * D_H_];
__device__ float g_agg1[(size_t)N2_ * D_H_];
__device__ float g_cnt1[N2_];
// bf16 split operand buffers (hi/lo)
__device__ __align__(128) __nv_bfloat16 g_A1h[(size_t)N1_ * 256];
__device__ __align__(128) __nv_bfloat16 g_A1l[(size_t)N1_ * 256];
__device__ __align__(128) __nv_bfloat16 g_A2h[(size_t)N2_ * 512];
__device__ __align__(128) __nv_bfloat16 g_A2l[(size_t)N2_ * 512];
__device__ __align__(128) __nv_bfloat16 g_B1h[256 * 256];
__device__ __align__(128) __nv_bfloat16 g_B1l[256 * 256];
__device__ __align__(128) __nv_bfloat16 g_B2h[128 * 512];
__device__ __align__(128) __nv_bfloat16 g_B2l[128 * 512];

// ---------------- ptx helpers (compute_103-safe: sm_80-era instructions) ----------------
__device__ __forceinline__ uint32_t smem_u32(const void* p) {
    uint32_t a;
    asm("{ .reg .u64 t; cvta.to.shared.u64 t, %1; cvt.u32.u64 %0, t; }" : "=r"(a) : "l"(p));
    return a;
}
__device__ __forceinline__ uint32_t sw128(uint32_t off) {
    return off ^ ((off >> 3) & 0x70);
}
__device__ __forceinline__ void cp16(uint32_t dst, const void* src, bool pred) {
    int sz = pred ? 16 : 0;
    asm volatile("cp.async.cg.shared.global [%0], [%1], 16, %2;"
                 :: "r"(dst), "l"(src), "r"(sz) : "memory");
}
__device__ __forceinline__ void ldsm4(uint32_t& r0, uint32_t& r1, uint32_t& r2, uint32_t& r3,
                                      uint32_t addr) {
    asm volatile("ldmatrix.sync.aligned.m8n8.x4.shared.b16 {%0,%1,%2,%3}, [%4];"
                 : "=r"(r0), "=r"(r1), "=r"(r2), "=r"(r3) : "r"(addr));
}
__device__ __forceinline__ void mma16816(float* c, uint32_t a0, uint32_t a1, uint32_t a2,
                                         uint32_t a3, uint32_t b0, uint32_t b1) {
    asm volatile(
        "mma.sync.aligned.m16n8k16.row.col.f32.bf16.bf16.f32 "
        "{%0,%1,%2,%3}, {%4,%5,%6,%7}, {%8,%9}, {%0,%1,%2,%3};"
        : "+f"(c[0]), "+f"(c[1]), "+f"(c[2]), "+f"(c[3])
        : "r"(a0), "r"(a1), "r"(a2), "r"(a3), "r"(b0), "r"(b1));
}

// ---------------- utility kernels ----------------
__global__ void zero4(float4* __restrict__ p, int n4) {
    int i = blockIdx.x * blockDim.x + threadIdx.x;
    if (i < n4) p[i] = make_float4(0.f, 0.f, 0.f, 0.f);
}

__device__ __forceinline__ void red_add_v4(float* ptr, float4 v) {
    asm volatile("red.global.add.v4.f32 [%0], {%1,%2,%3,%4};"
                 :: "l"(ptr), "f"(v.x), "f"(v.y), "f"(v.z), "f"(v.w)
                 : "memory");
}

template<int D>
__global__ void scatter_edges(const float* __restrict__ feat,
                              const int* __restrict__ src,
                              const int* __restrict__ dst,
                              float* __restrict__ agg,
                              float* __restrict__ cnt, int nE) {
    int gw   = (blockIdx.x * blockDim.x + threadIdx.x) >> 5;
    int lane = threadIdx.x & 31;
    if (gw >= nE) return;
    int s = src[gw];
    int d = dst[gw];
    const float4* fs = (const float4*)(feat + (size_t)s * D);
    float* ag = agg + (size_t)d * D;
    #pragma unroll
    for (int j = 0; j < D / 128; j++) {
        float4 v = fs[j * 32 + lane];
        red_add_v4(ag + (size_t)(j * 32 + lane) * 4, v);
    }
    if (lane == 0) atomicAdd(&cnt[d], 1.0f);
}

template<int D>
__global__ void meanify(float* __restrict__ agg, const float* __restrict__ cnt, int n) {
    int i = blockIdx.x * blockDim.x + threadIdx.x;
    int total = n * (D / 4);
    if (i >= total) return;
    int row = i / (D / 4);
    float inv = 1.0f / fmaxf(cnt[row], 1.0f);
    float4* p = (float4*)agg + i;
    float4 v = *p;
    v.x *= inv; v.y *= inv; v.z *= inv; v.w *= inv;
    *p = v;
}

// concat two fp32 sources along K and split each element into bf16 hi + lo
__global__ void split_cat(const float* __restrict__ s0, const float* __restrict__ s1,
                          __nv_bfloat16* __restrict__ hi, __nv_bfloat16* __restrict__ lo,
                          int rows, int K0, int K1) {
    int Kt = K0 + K1;
    int i = blockIdx.x * blockDim.x + threadIdx.x;
    int tot = rows * (Kt / 4);
    if (i >= tot) return;
    int row = i / (Kt / 4);
    int c4 = (i % (Kt / 4)) * 4;
    float4 v = (c4 < K0) ? *(const float4*)(s0 + (size_t)row * K0 + c4)
                         : *(const float4*)(s1 + (size_t)row * K1 + (c4 - K0));
    float f[4] = {v.x, v.y, v.z, v.w};
    alignas(8) __nv_bfloat16 h[4];
    alignas(8) __nv_bfloat16 l[4];
    #pragma unroll
    for (int j = 0; j < 4; j++) {
        h[j] = __float2bfloat16(f[j]);
        l[j] = __float2bfloat16(f[j] - __bfloat162float(h[j]));
    }
    *(uint2*)(hi + (size_t)row * Kt + c4) = *(uint2*)h;
    *(uint2*)(lo + (size_t)row * Kt + c4) = *(uint2*)l;
}

// ---------------- mma.sync bf16 GEMM ----------------
// C[M,BN] = opt_relu( split3( A[M,K] @ B[BN,K]^T ) + bias )
// 3 passes: Ah*Bh + Ah*Bl + Al*Bh accumulated in fp32 registers.
// 256 threads, 8 warps (2 M x 4 N), warp tile 64 x (BN/4).
template<int BN, int K, bool RELU>
__global__ void __launch_bounds__(256, 1)
gemm_mma(const __nv_bfloat16* __restrict__ Ah, const __nv_bfloat16* __restrict__ Al,
         const __nv_bfloat16* __restrict__ Bh, const __nv_bfloat16* __restrict__ Bl,
         const float* __restrict__ bias, float* __restrict__ C, int M) {
    constexpr int KC = 64;                 // bf16 K per chunk (128B rows)
    constexpr int NCP = K / KC;
    constexpr int NCHUNK = 3 * NCP;
    constexpr int ATILE = 128 * 128;       // bytes
    constexpr int BTILE = BN * 128;
    constexpr int WN = BN / 4;             // warp tile N
    constexpr int MT = 4;                  // 64/16 m-tiles per warp
    constexpr int NT = WN / 8;             // n8 tiles per warp
    constexpr int NG = (1024 + BN * 8) / 256;  // cp.async granules per thread

    extern __shared__ char dsm[];
    char* tb = (char*)((((uintptr_t)dsm) + 1023) & ~(uintptr_t)1023);
    const uint32_t aBase[2] = { smem_u32(tb),             smem_u32(tb + ATILE) };
    const uint32_t bBase[2] = { smem_u32(tb + 2 * ATILE), smem_u32(tb + 2 * ATILE + BTILE) };

    const int tid  = threadIdx.x;
    const int wid  = tid >> 5;
    const int lane = tid & 31;
    const int m0   = blockIdx.x * 128;
    const int wm0  = (wid >> 2) * 64;      // warp M origin within CTA tile
    const int wn0  = (wid & 3) * WN;       // warp N origin

    float acc[MT][NT][4];
    #pragma unroll
    for (int i = 0; i < MT; i++)
        #pragma unroll
        for (int j = 0; j < NT; j++)
            #pragma unroll
            for (int e = 0; e < 4; e++) acc[i][j][e] = 0.f;

    auto load_chunk = [&](int ch, int buf) {
        const int pass = ch / NCP;
        const int kc = (ch % NCP) * KC;
        const __nv_bfloat16* As = (pass < 2) ? Ah : Al;
        const __nv_bfloat16* Bs = (pass == 1) ? Bl : Bh;
        #pragma unroll
        for (int it = 0; it < NG; it++) {
            int g = tid + it * 256;
            if (g < 1024) {                      // A: 128 rows x 8 granules
                int row = g >> 3, c = g & 7;
                int gr = m0 + row;
                bool ok = gr < M;
                int grs = ok ? gr : (M - 1);
                cp16(aBase[buf] + sw128((uint32_t)(row * 128 + c * 16)),
                     As + (size_t)grs * K + kc + c * 8, ok);
            } else {                             // B: BN rows x 8 granules
                int g2 = g - 1024;
                int row = g2 >> 3, c = g2 & 7;
                cp16(bBase[buf] + sw128((uint32_t)(row * 128 + c * 16)),
                     Bs + (size_t)row * K + kc + c * 8, true);
            }
        }
        asm volatile("cp.async.commit_group;" ::: "memory");
    };

    load_chunk(0, 0);

    for (int ch = 0; ch < NCHUNK; ch++) {
        const int buf = ch & 1;
        if (ch + 1 < NCHUNK) {
            load_chunk(ch + 1, buf ^ 1);
            asm volatile("cp.async.wait_group 1;" ::: "memory");
        } else {
            asm volatile("cp.async.wait_group 0;" ::: "memory");
        }
        __syncthreads();

        const uint32_t aB = aBase[buf];
        const uint32_t bB = bBase[buf];
        #pragma unroll
        for (int ks = 0; ks < 4; ks++) {
            const int kb = ks * 32;              // byte offset of k16 within 128B row
            // B fragments: ldmatrix x4 covers two n8 tiles
            uint32_t bf[NT][2];
            #pragma unroll
            for (int nt2 = 0; nt2 < NT / 2; nt2++) {
                int n0 = wn0 + nt2 * 16;
                int rsel = (lane & 7) + ((lane >> 4) << 3);  // +8 for lanes 16..31
                int ksel = (lane >> 3) & 1;                  // khi for groups 1,3
                uint32_t off = (uint32_t)((n0 + rsel) * 128 + kb + ksel * 16);
                ldsm4(bf[2 * nt2][0], bf[2 * nt2][1],
                      bf[2 * nt2 + 1][0], bf[2 * nt2 + 1][1], bB + sw128(off));
            }
            // A fragments + mma
            #pragma unroll
            for (int mt = 0; mt < MT; mt++) {
                int mrow = wm0 + mt * 16;
                int rsel = (lane & 7) + (((lane >> 3) & 1) << 3);  // +8 for groups 1,3
                int ksel = lane >> 4;                              // khi for lanes>=16
                uint32_t off = (uint32_t)((mrow + rsel) * 128 + kb + ksel * 16);
                uint32_t a0, a1, a2, a3;
                ldsm4(a0, a1, a2, a3, aB + sw128(off));
                #pragma unroll
                for (int nt = 0; nt < NT; nt++)
                    mma16816(acc[mt][nt], a0, a1, a2, a3, bf[nt][0], bf[nt][1]);
            }
        }
        __syncthreads();
    }

    // epilogue: + bias, optional relu
    #pragma unroll
    for (int mt = 0; mt < MT; mt++) {
        int r0 = m0 + wm0 + mt * 16 + (lane >> 2);
        int r1 = r0 + 8;
        #pragma unroll
        for (int nt = 0; nt < NT; nt++) {
            int c = wn0 + nt * 8 + (lane & 3) * 2;
            float2 bv = *(const float2*)(bias + c);
            if (r0 < M) {
                float2 v = make_float2(acc[mt][nt][0] + bv.x, acc[mt][nt][1] + bv.y);
                if (RELU) { v.x = fmaxf(v.x, 0.f); v.y = fmaxf(v.y, 0.f); }
                *(float2*)(C + (size_t)r0 * BN + c) = v;
            }
            if (r1 < M) {
                float2 v = make_float2(acc[mt][nt][2] + bv.x, acc[mt][nt][3] + bv.y);
                if (RELU) { v.x = fmaxf(v.x, 0.f); v.y = fmaxf(v.y, 0.f); }
                *(float2*)(C + (size_t)r1 * BN + c) = v;
            }
        }
    }
}

// ---------------- host side ----------------
extern "C" void kernel_launch(void* const* d_in, const int* in_sizes, int n_in,
                              void* d_out, int out_size) {
    const float* x   = (const float*)d_in[0];
    const float* Wl0 = (const float*)d_in[1];
    const float* bl0 = (const float*)d_in[2];
    const float* Wr0 = (const float*)d_in[3];
    const float* Wl1 = (const float*)d_in[4];
    const float* bl1 = (const float*)d_in[5];
    const float* Wr1 = (const float*)d_in[6];
    const int* e0s = (const int*)d_in[7];
    const int* e0d = (const int*)d_in[8];
    const int* e1s = (const int*)d_in[9];
    const int* e1d = (const int*)d_in[10];
    float* out = (float*)d_out;

    float *agg0, *cnt0, *h, *agg1, *cnt1;
    __nv_bfloat16 *A1h, *A1l, *A2h, *A2l, *B1h, *B1l, *B2h, *B2l;
    cudaGetSymbolAddress((void**)&agg0, g_agg0);
    cudaGetSymbolAddress((void**)&cnt0, g_cnt0);
    cudaGetSymbolAddress((void**)&h,    g_h);
    cudaGetSymbolAddress((void**)&agg1, g_agg1);
    cudaGetSymbolAddress((void**)&cnt1, g_cnt1);
    cudaGetSymbolAddress((void**)&A1h, g_A1h);
    cudaGetSymbolAddress((void**)&A1l, g_A1l);
    cudaGetSymbolAddress((void**)&A2h, g_A2h);
    cudaGetSymbolAddress((void**)&A2l, g_A2l);
    cudaGetSymbolAddress((void**)&B1h, g_B1h);
    cudaGetSymbolAddress((void**)&B1l, g_B1l);
    cudaGetSymbolAddress((void**)&B2h, g_B2h);
    cudaGetSymbolAddress((void**)&B2l, g_B2l);

    const int smem1 = 1024 + 2 * (128 * 128) + 2 * (256 * 128);  // 99328
    const int smem2 = 1024 + 2 * (128 * 128) + 2 * (128 * 128);  // 66560
    cudaFuncSetAttribute(gemm_mma<256, 256, true>,
                         cudaFuncAttributeMaxDynamicSharedMemorySize, smem1);
    cudaFuncSetAttribute(gemm_mma<128, 512, false>,
                         cudaFuncAttributeMaxDynamicSharedMemorySize, smem2);

    // zero accumulators
    {
        int n4 = N1_ * D_IN_ / 4;
        zero4<<<(n4 + 255) / 256, 256>>>((float4*)agg0, n4);
        n4 = N1_ / 4;
        zero4<<<(n4 + 255) / 256, 256>>>((float4*)cnt0, n4);
        n4 = N2_ * D_H_ / 4;
        zero4<<<(n4 + 255) / 256, 256>>>((float4*)agg1, n4);
        n4 = N2_ / 4;
        zero4<<<(n4 + 255) / 256, 256>>>((float4*)cnt1, n4);
    }

    // weight concat+split (tiny)
    {
        int t = 256 * (256 / 4);
        split_cat<<<(t + 255) / 256, 256>>>(Wl0, Wr0, B1h, B1l, 256, 128, 128);
        t = 128 * (512 / 4);
        split_cat<<<(t + 255) / 256, 256>>>(Wl1, Wr1, B2h, B2l, 128, 256, 256);
    }

    // hop 0 aggregation
    {
        long long thr = (long long)E0_ * 32;
        scatter_edges<D_IN_><<<(int)((thr + 255) / 256), 256>>>(x, e0s, e0d, agg0, cnt0, E0_);
        int t = N1_ * (D_IN_ / 4);
        meanify<D_IN_><<<(t + 255) / 256, 256>>>(agg0, cnt0, N1_);
    }

    // A1 = [mean_agg0 | x[:N1]] split to bf16 hi/lo
    {
        int t = N1_ * (256 / 4);
        split_cat<<<(t + 255) / 256, 256>>>(agg0, x, A1h, A1l, N1_, 128, 128);
    }

    // h = relu(A1 @ B1^T + bl0)   [N1, 256]
    {
        dim3 grid((N1_ + 127) / 128);
        gemm_mma<256, 256, true><<<grid, 256, smem1>>>(A1h, A1l, B1h, B1l, bl0, h, N1_);
    }

    // hop 1 aggregation
    {
        long long thr = (long long)E1_ * 32;
        scatter_edges<D_H_><<<(int)((thr + 255) / 256), 256>>>(h, e1s, e1d, agg1, cnt1, E1_);
        int t = N2_ * (D_H_ / 4);
        meanify<D_H_><<<(t + 255) / 256, 256>>>(agg1, cnt1, N2_);
    }

    // A2 = [mean_agg1 | h[:N2]] split
    {
        int t = N2_ * (512 / 4);
        split_cat<<<(t + 255) / 256, 256>>>(agg1, h, A2h, A2l, N2_, 256, 256);
    }

    // out = A2 @ B2^T + bl1   [N2, 128]
    {
        dim3 grid((N2_ + 127) / 128);
        gemm_mma<128, 512, false><<<grid, 256, smem2>>>(A2h, A2l, B2h, B2l, bl1, out, N2_);
    }
}

// round 5
// speedup vs baseline: 1.4642x; 1.0270x over previous
#include <cuda_runtime.h>
#include <cuda_bf16.h>
#include <cstdint>

#define N0_   500000
#define N1_   100000
#define N2_   25000
#define E0_   1600000
#define E1_   400000
#define D_IN_ 128
#define D_H_  256
#define D_OUT_ 128

// ---- scratch (allocation-free rule: __device__ globals) ----
__device__ float g_agg0[(size_t)N1_ * D_IN_];
__device__ float g_cnt0[N1_];
__device__ float g_h[(size_t)N1_ * D_H_];
__device__ float g_agg1[(size_t)N2_ * D_H_];
__device__ float g_cnt1[N2_];
// bf16 split operand buffers (hi/lo)
__device__ __align__(128) __nv_bfloat16 g_A1h[(size_t)N1_ * 256];
__device__ __align__(128) __nv_bfloat16 g_A1l[(size_t)N1_ * 256];
__device__ __align__(128) __nv_bfloat16 g_A2h[(size_t)N2_ * 512];
__device__ __align__(128) __nv_bfloat16 g_A2l[(size_t)N2_ * 512];
__device__ __align__(128) __nv_bfloat16 g_B1h[256 * 256];
__device__ __align__(128) __nv_bfloat16 g_B1l[256 * 256];
__device__ __align__(128) __nv_bfloat16 g_B2h[128 * 512];
__device__ __align__(128) __nv_bfloat16 g_B2l[128 * 512];

// ---------------- ptx helpers (compute_103-safe) ----------------
__device__ __forceinline__ uint32_t smem_u32(const void* p) {
    uint32_t a;
    asm("{ .reg .u64 t; cvta.to.shared.u64 t, %1; cvt.u32.u64 %0, t; }" : "=r"(a) : "l"(p));
    return a;
}
__device__ __forceinline__ uint32_t sw128(uint32_t off) {
    return off ^ ((off >> 3) & 0x70);
}
__device__ __forceinline__ void cp16(uint32_t dst, const void* src, bool pred) {
    int sz = pred ? 16 : 0;
    asm volatile("cp.async.cg.shared.global [%0], [%1], 16, %2;"
                 :: "r"(dst), "l"(src), "r"(sz) : "memory");
}
__device__ __forceinline__ void ldsm4(uint32_t& r0, uint32_t& r1, uint32_t& r2, uint32_t& r3,
                                      uint32_t addr) {
    asm volatile("ldmatrix.sync.aligned.m8n8.x4.shared.b16 {%0,%1,%2,%3}, [%4];"
                 : "=r"(r0), "=r"(r1), "=r"(r2), "=r"(r3) : "r"(addr));
}
__device__ __forceinline__ void mma16816(float* c, uint32_t a0, uint32_t a1, uint32_t a2,
                                         uint32_t a3, uint32_t b0, uint32_t b1) {
    asm volatile(
        "mma.sync.aligned.m16n8k16.row.col.f32.bf16.bf16.f32 "
        "{%0,%1,%2,%3}, {%4,%5,%6,%7}, {%8,%9}, {%0,%1,%2,%3};"
        : "+f"(c[0]), "+f"(c[1]), "+f"(c[2]), "+f"(c[3])
        : "r"(a0), "r"(a1), "r"(a2), "r"(a3), "r"(b0), "r"(b1));
}
__device__ __forceinline__ uint32_t pack_bf16x2(float a, float b) {
    __nv_bfloat162 p = __floats2bfloat162_rn(a, b);
    return *(uint32_t*)&p;
}

// ---------------- utility kernels ----------------
__global__ void zero_all(float4* a0, float4* c0, float4* a1, float4* c1) {
    const int n1 = N1_ * D_IN_ / 4, n2 = N1_ / 4, n3 = N2_ * D_H_ / 4, n4 = N2_ / 4;
    int i = blockIdx.x * blockDim.x + threadIdx.x;
    float4 z = make_float4(0.f, 0.f, 0.f, 0.f);
    if (i < n1) a0[i] = z;
    else if (i < n1 + n2) c0[i - n1] = z;
    else if (i < n1 + n2 + n3) a1[i - n1 - n2] = z;
    else if (i < n1 + n2 + n3 + n4) c1[i - n1 - n2 - n3] = z;
}

__device__ __forceinline__ void red_add_v4(float* ptr, float4 v) {
    asm volatile("red.global.add.v4.f32 [%0], {%1,%2,%3,%4};"
                 :: "l"(ptr), "f"(v.x), "f"(v.y), "f"(v.z), "f"(v.w)
                 : "memory");
}

template<int D>
__global__ void scatter_edges(const float* __restrict__ feat,
                              const int* __restrict__ src,
                              const int* __restrict__ dst,
                              float* __restrict__ agg,
                              float* __restrict__ cnt, int nE) {
    int gw   = (blockIdx.x * blockDim.x + threadIdx.x) >> 5;
    int lane = threadIdx.x & 31;
    if (gw >= nE) return;
    int s = src[gw];
    int d = dst[gw];
    const float4* fs = (const float4*)(feat + (size_t)s * D);
    float* ag = agg + (size_t)d * D;
    #pragma unroll
    for (int j = 0; j < D / 128; j++) {
        float4 v = fs[j * 32 + lane];
        red_add_v4(ag + (size_t)(j * 32 + lane) * 4, v);
    }
    if (lane == 0) atomicAdd(&cnt[d], 1.0f);
}

// split fp32 -> bf16 hi/lo. First Kagg cols come from agg (scaled by 1/max(cnt,1)),
// next Kx cols from xsrc. Output row stride Kt.
__global__ void mean_split(const float* __restrict__ agg, const float* __restrict__ cnt,
                           const float* __restrict__ xsrc,
                           __nv_bfloat16* __restrict__ hi, __nv_bfloat16* __restrict__ lo,
                           int rows, int Kagg, int Kx, int Kt) {
    int Ks = Kagg + Kx;
    int i = blockIdx.x * blockDim.x + threadIdx.x;
    int tot = rows * (Ks / 4);
    if (i >= tot) return;
    int row = i / (Ks / 4);
    int c4 = (i % (Ks / 4)) * 4;
    float4 v;
    if (c4 < Kagg) {
        v = *(const float4*)(agg + (size_t)row * Kagg + c4);
        float inv = 1.0f / fmaxf(cnt[row], 1.0f);
        v.x *= inv; v.y *= inv; v.z *= inv; v.w *= inv;
    } else {
        v = *(const float4*)(xsrc + (size_t)row * Kx + (c4 - Kagg));
    }
    float f[4] = {v.x, v.y, v.z, v.w};
    alignas(8) __nv_bfloat16 h[4];
    alignas(8) __nv_bfloat16 l[4];
    #pragma unroll
    for (int j = 0; j < 4; j++) {
        h[j] = __float2bfloat16(f[j]);
        l[j] = __float2bfloat16(f[j] - __bfloat162float(h[j]));
    }
    *(uint2*)(hi + (size_t)row * Kt + c4) = *(uint2*)h;
    *(uint2*)(lo + (size_t)row * Kt + c4) = *(uint2*)l;
}

// concat two fp32 sources along K and split into bf16 hi/lo (for weights)
__global__ void split_cat(const float* __restrict__ s0, const float* __restrict__ s1,
                          __nv_bfloat16* __restrict__ hi, __nv_bfloat16* __restrict__ lo,
                          int rows, int K0, int K1) {
    int Kt = K0 + K1;
    int i = blockIdx.x * blockDim.x + threadIdx.x;
    int tot = rows * (Kt / 4);
    if (i >= tot) return;
    int row = i / (Kt / 4);
    int c4 = (i % (Kt / 4)) * 4;
    float4 v = (c4 < K0) ? *(const float4*)(s0 + (size_t)row * K0 + c4)
                         : *(const float4*)(s1 + (size_t)row * K1 + (c4 - K0));
    float f[4] = {v.x, v.y, v.z, v.w};
    alignas(8) __nv_bfloat16 h[4];
    alignas(8) __nv_bfloat16 l[4];
    #pragma unroll
    for (int j = 0; j < 4; j++) {
        h[j] = __float2bfloat16(f[j]);
        l[j] = __float2bfloat16(f[j] - __bfloat162float(h[j]));
    }
    *(uint2*)(hi + (size_t)row * Kt + c4) = *(uint2*)h;
    *(uint2*)(lo + (size_t)row * Kt + c4) = *(uint2*)l;
}

// ---------------- mma.sync bf16 GEMM (3-stage cp.async pipeline) ----------------
// C[M,BN] = opt_relu( split3( A[M,K] @ B[BN,K]^T ) + bias )
// If WSPLIT: rows < n2 also emit bf16 hi/lo into A2 buffers at col offset 256, stride 512.
template<int BN, int K, bool RELU, bool WSPLIT>
__global__ void __launch_bounds__(256, 1)
gemm_mma(const __nv_bfloat16* __restrict__ Ah, const __nv_bfloat16* __restrict__ Al,
         const __nv_bfloat16* __restrict__ Bh, const __nv_bfloat16* __restrict__ Bl,
         const float* __restrict__ bias, float* __restrict__ C, int M,
         __nv_bfloat16* __restrict__ A2h, __nv_bfloat16* __restrict__ A2l, int n2) {
    constexpr int STAGES = 3;
    constexpr int KC = 64;
    constexpr int NCP = K / KC;
    constexpr int NCHUNK = 3 * NCP;
    constexpr int ATILE = 128 * 128;
    constexpr int BTILE = BN * 128;
    constexpr int STILE = ATILE + BTILE;
    constexpr int WN = BN / 4;
    constexpr int MT = 4;
    constexpr int NT = WN / 8;
    constexpr int NG = (1024 + BN * 8) / 256;

    extern __shared__ char dsm[];
    char* tb = (char*)((((uintptr_t)dsm) + 1023) & ~(uintptr_t)1023);
    uint32_t aBase[STAGES], bBase[STAGES];
    #pragma unroll
    for (int s = 0; s < STAGES; s++) {
        aBase[s] = smem_u32(tb + s * STILE);
        bBase[s] = smem_u32(tb + s * STILE + ATILE);
    }

    const int tid  = threadIdx.x;
    const int wid  = tid >> 5;
    const int lane = tid & 31;
    const int m0   = blockIdx.x * 128;
    const int wm0  = (wid >> 2) * 64;
    const int wn0  = (wid & 3) * WN;

    float acc[MT][NT][4];
    #pragma unroll
    for (int i = 0; i < MT; i++)
        #pragma unroll
        for (int j = 0; j < NT; j++)
            #pragma unroll
            for (int e = 0; e < 4; e++) acc[i][j][e] = 0.f;

    auto load_chunk = [&](int ch, int buf) {
        const int pass = ch / NCP;
        const int kc = (ch % NCP) * KC;
        const __nv_bfloat16* As = (pass < 2) ? Ah : Al;
        const __nv_bfloat16* Bs = (pass == 1) ? Bl : Bh;
        #pragma unroll
        for (int it = 0; it < NG; it++) {
            int g = tid + it * 256;
            if (g < 1024) {
                int row = g >> 3, c = g & 7;
                int gr = m0 + row;
                bool ok = gr < M;
                int grs = ok ? gr : (M - 1);
                cp16(aBase[buf] + sw128((uint32_t)(row * 128 + c * 16)),
                     As + (size_t)grs * K + kc + c * 8, ok);
            } else {
                int g2 = g - 1024;
                int row = g2 >> 3, c = g2 & 7;
                cp16(bBase[buf] + sw128((uint32_t)(row * 128 + c * 16)),
                     Bs + (size_t)row * K + kc + c * 8, true);
            }
        }
        asm volatile("cp.async.commit_group;" ::: "memory");
    };

    #pragma unroll
    for (int s = 0; s < STAGES - 1; s++) load_chunk(s, s);

    for (int ch = 0; ch < NCHUNK; ch++) {
        const int buf = ch % STAGES;
        if (ch == NCHUNK - 1)
            asm volatile("cp.async.wait_group 0;" ::: "memory");
        else
            asm volatile("cp.async.wait_group %0;" :: "n"(STAGES - 2) : "memory");
        __syncthreads();
        int nx = ch + STAGES - 1;
        if (nx < NCHUNK) load_chunk(nx, nx % STAGES);

        const uint32_t aB = aBase[buf];
        const uint32_t bB = bBase[buf];
        #pragma unroll
        for (int ks = 0; ks < 4; ks++) {
            const int kb = ks * 32;
            uint32_t bf[NT][2];
            #pragma unroll
            for (int nt2 = 0; nt2 < NT / 2; nt2++) {
                int n0 = wn0 + nt2 * 16;
                int rsel = (lane & 7) + ((lane >> 4) << 3);
                int ksel = (lane >> 3) & 1;
                uint32_t off = (uint32_t)((n0 + rsel) * 128 + kb + ksel * 16);
                ldsm4(bf[2 * nt2][0], bf[2 * nt2][1],
                      bf[2 * nt2 + 1][0], bf[2 * nt2 + 1][1], bB + sw128(off));
            }
            #pragma unroll
            for (int mt = 0; mt < MT; mt++) {
                int mrow = wm0 + mt * 16;
                int rsel = (lane & 7) + (((lane >> 3) & 1) << 3);
                int ksel = lane >> 4;
                uint32_t off = (uint32_t)((mrow + rsel) * 128 + kb + ksel * 16);
                uint32_t a0, a1, a2, a3;
                ldsm4(a0, a1, a2, a3, aB + sw128(off));
                #pragma unroll
                for (int nt = 0; nt < NT; nt++)
                    mma16816(acc[mt][nt], a0, a1, a2, a3, bf[nt][0], bf[nt][1]);
            }
        }
    }

    // epilogue
    #pragma unroll
    for (int mt = 0; mt < MT; mt++) {
        int rr[2];
        rr[0] = m0 + wm0 + mt * 16 + (lane >> 2);
        rr[1] = rr[0] + 8;
        #pragma unroll
        for (int nt = 0; nt < NT; nt++) {
            int c = wn0 + nt * 8 + (lane & 3) * 2;
            float2 bv = *(const float2*)(bias + c);
            #pragma unroll
            for (int half = 0; half < 2; half++) {
                int r = rr[half];
                if (r < M) {
                    float2 v = make_float2(acc[mt][nt][2 * half + 0] + bv.x,
                                           acc[mt][nt][2 * half + 1] + bv.y);
                    if (RELU) { v.x = fmaxf(v.x, 0.f); v.y = fmaxf(v.y, 0.f); }
                    *(float2*)(C + (size_t)r * BN + c) = v;
                    if (WSPLIT && r < n2) {
                        float hx = __bfloat162float(__float2bfloat16(v.x));
                        float hy = __bfloat162float(__float2bfloat16(v.y));
                        size_t o = (size_t)r * 512 + 256 + c;
                        *(uint32_t*)(A2h + o) = pack_bf16x2(hx, hy);
                        *(uint32_t*)(A2l + o) = pack_bf16x2(v.x - hx, v.y - hy);
                    }
                }
            }
        }
    }
}

// ---------------- host side ----------------
extern "C" void kernel_launch(void* const* d_in, const int* in_sizes, int n_in,
                              void* d_out, int out_size) {
    const float* x   = (const float*)d_in[0];
    const float* Wl0 = (const float*)d_in[1];
    const float* bl0 = (const float*)d_in[2];
    const float* Wr0 = (const float*)d_in[3];
    const float* Wl1 = (const float*)d_in[4];
    const float* bl1 = (const float*)d_in[5];
    const float* Wr1 = (const float*)d_in[6];
    const int* e0s = (const int*)d_in[7];
    const int* e0d = (const int*)d_in[8];
    const int* e1s = (const int*)d_in[9];
    const int* e1d = (const int*)d_in[10];
    float* out = (float*)d_out;

    float *agg0, *cnt0, *h, *agg1, *cnt1;
    __nv_bfloat16 *A1h, *A1l, *A2h, *A2l, *B1h, *B1l, *B2h, *B2l;
    cudaGetSymbolAddress((void**)&agg0, g_agg0);
    cudaGetSymbolAddress((void**)&cnt0, g_cnt0);
    cudaGetSymbolAddress((void**)&h,    g_h);
    cudaGetSymbolAddress((void**)&agg1, g_agg1);
    cudaGetSymbolAddress((void**)&cnt1, g_cnt1);
    cudaGetSymbolAddress((void**)&A1h, g_A1h);
    cudaGetSymbolAddress((void**)&A1l, g_A1l);
    cudaGetSymbolAddress((void**)&A2h, g_A2h);
    cudaGetSymbolAddress((void**)&A2l, g_A2l);
    cudaGetSymbolAddress((void**)&B1h, g_B1h);
    cudaGetSymbolAddress((void**)&B1l, g_B1l);
    cudaGetSymbolAddress((void**)&B2h, g_B2h);
    cudaGetSymbolAddress((void**)&B2l, g_B2l);

    const int smem1 = 1024 + 3 * (128 * 128 + 256 * 128);  // 148480
    const int smem2 = 1024 + 3 * (128 * 128 + 128 * 128);  // 99328
    cudaFuncSetAttribute(gemm_mma<256, 256, true, true>,
                         cudaFuncAttributeMaxDynamicSharedMemorySize, smem1);
    cudaFuncSetAttribute(gemm_mma<128, 512, false, false>,
                         cudaFuncAttributeMaxDynamicSharedMemorySize, smem2);

    // L0: zero accumulators (one kernel)
    {
        int tot = N1_ * D_IN_ / 4 + N1_ / 4 + N2_ * D_H_ / 4 + N2_ / 4;
        zero_all<<<(tot + 255) / 256, 256>>>((float4*)agg0, (float4*)cnt0,
                                             (float4*)agg1, (float4*)cnt1);
    }
    // L1, L2: weight splits
    {
        int t = 256 * (256 / 4);
        split_cat<<<(t + 255) / 256, 256>>>(Wl0, Wr0, B1h, B1l, 256, 128, 128);
        t = 128 * (512 / 4);
        split_cat<<<(t + 255) / 256, 256>>>(Wl1, Wr1, B2h, B2l, 128, 256, 256);
    }
    // L3: hop-0 scatter
    {
        long long thr = (long long)E0_ * 32;
        scatter_edges<D_IN_><<<(int)((thr + 255) / 256), 256>>>(x, e0s, e0d, agg0, cnt0, E0_);
    }
    // L4: A1 = [mean(agg0) | x[:N1]] -> bf16 hi/lo (mean fused)
    {
        int t = N1_ * (256 / 4);
        mean_split<<<(t + 255) / 256, 256>>>(agg0, cnt0, x, A1h, A1l, N1_, 128, 128, 256);
    }
    // L5: h = relu(A1 @ B1^T + bl0); also emits A2 right half (h[:N2]) hi/lo
    {
        dim3 grid((N1_ + 127) / 128);
        gemm_mma<256, 256, true, true><<<grid, 256, smem1>>>(
            A1h, A1l, B1h, B1l, bl0, h, N1_, A2h, A2l, N2_);
    }
    // L6: hop-1 scatter
    {
        long long thr = (long long)E1_ * 32;
        scatter_edges<D_H_><<<(int)((thr + 255) / 256), 256>>>(h, e1s, e1d, agg1, cnt1, E1_);
    }
    // L7: A2 left half = mean(agg1) -> bf16 hi/lo (row stride 512)
    {
        int t = N2_ * (256 / 4);
        mean_split<<<(t + 255) / 256, 256>>>(agg1, cnt1, (const float*)nullptr,
                                             A2h, A2l, N2_, 256, 0, 512);
    }
    // L8: out = A2 @ B2^T + bl1
    {
        dim3 grid((N2_ + 127) / 128);
        gemm_mma<128, 512, false, false><<<grid, 256, smem2>>>(
            A2h, A2l, B2h, B2l, bl1, out, N2_, (__nv_bfloat16*)nullptr,
            (__nv_bfloat16*)nullptr, 0);
    }
}

// round 6
// speedup vs baseline: 1.4694x; 1.0036x over previous
#include <cuda_runtime.h>
#include <cuda_bf16.h>
#include <cstdint>

#define N0_   500000
#define N1_   100000
#define N2_   25000
#define E0_   1600000
#define E1_   400000
#define D_IN_ 128
#define D_H_  256
#define D_OUT_ 128

// ---- scratch (allocation-free rule: __device__ globals) ----
__device__ float g_agg0[(size_t)N1_ * D_IN_];
__device__ float g_cnt0[N1_];
__device__ float g_h[(size_t)N1_ * D_H_];
__device__ float g_agg1[(size_t)N2_ * D_H_];
__device__ float g_cnt1[N2_];
// bf16 split operand buffers (hi/lo)
__device__ __align__(128) __nv_bfloat16 g_A1h[(size_t)N1_ * 256];
__device__ __align__(128) __nv_bfloat16 g_A1l[(size_t)N1_ * 256];
__device__ __align__(128) __nv_bfloat16 g_A2h[(size_t)N2_ * 512];
__device__ __align__(128) __nv_bfloat16 g_A2l[(size_t)N2_ * 512];
__device__ __align__(128) __nv_bfloat16 g_B1h[256 * 256];
__device__ __align__(128) __nv_bfloat16 g_B1l[256 * 256];
__device__ __align__(128) __nv_bfloat16 g_B2h[128 * 512];
__device__ __align__(128) __nv_bfloat16 g_B2l[128 * 512];

// ---------------- ptx helpers (compute_103-safe) ----------------
__device__ __forceinline__ uint32_t smem_u32(const void* p) {
    uint32_t a;
    asm("{ .reg .u64 t; cvta.to.shared.u64 t, %1; cvt.u32.u64 %0, t; }" : "=r"(a) : "l"(p));
    return a;
}
__device__ __forceinline__ uint32_t sw128(uint32_t off) {
    return off ^ ((off >> 3) & 0x70);
}
__device__ __forceinline__ void cp16(uint32_t dst, const void* src, bool pred) {
    int sz = pred ? 16 : 0;
    asm volatile("cp.async.cg.shared.global [%0], [%1], 16, %2;"
                 :: "r"(dst), "l"(src), "r"(sz) : "memory");
}
__device__ __forceinline__ void ldsm4(uint32_t& r0, uint32_t& r1, uint32_t& r2, uint32_t& r3,
                                      uint32_t addr) {
    asm volatile("ldmatrix.sync.aligned.m8n8.x4.shared.b16 {%0,%1,%2,%3}, [%4];"
                 : "=r"(r0), "=r"(r1), "=r"(r2), "=r"(r3) : "r"(addr));
}
__device__ __forceinline__ void mma16816(float* c, uint32_t a0, uint32_t a1, uint32_t a2,
                                         uint32_t a3, uint32_t b0, uint32_t b1) {
    asm volatile(
        "mma.sync.aligned.m16n8k16.row.col.f32.bf16.bf16.f32 "
        "{%0,%1,%2,%3}, {%4,%5,%6,%7}, {%8,%9}, {%0,%1,%2,%3};"
        : "+f"(c[0]), "+f"(c[1]), "+f"(c[2]), "+f"(c[3])
        : "r"(a0), "r"(a1), "r"(a2), "r"(a3), "r"(b0), "r"(b1));
}
__device__ __forceinline__ uint32_t pack_bf16x2(float a, float b) {
    __nv_bfloat162 p = __floats2bfloat162_rn(a, b);
    return *(uint32_t*)&p;
}

// ---------------- utility kernels ----------------
__global__ void zero_all(float4* a0, float4* c0, float4* a1, float4* c1) {
    const int n1 = N1_ * D_IN_ / 4, n2 = N1_ / 4, n3 = N2_ * D_H_ / 4, n4 = N2_ / 4;
    int i = blockIdx.x * blockDim.x + threadIdx.x;
    float4 z = make_float4(0.f, 0.f, 0.f, 0.f);
    if (i < n1) a0[i] = z;
    else if (i < n1 + n2) c0[i - n1] = z;
    else if (i < n1 + n2 + n3) a1[i - n1 - n2] = z;
    else if (i < n1 + n2 + n3 + n4) c1[i - n1 - n2 - n3] = z;
}

__device__ __forceinline__ void red_add_v4(float* ptr, float4 v) {
    asm volatile("red.global.add.v4.f32 [%0], {%1,%2,%3,%4};"
                 :: "l"(ptr), "f"(v.x), "f"(v.y), "f"(v.z), "f"(v.w)
                 : "memory");
}

// src-range-pass scatter: the grid is P contiguous groups of blocks; group p only
// gathers edges with src in [p*nSrc/P, (p+1)*nSrc/P), so concurrently-scheduled
// CTAs touch an L2-resident slice of `feat`. Each warp screens 8 edges at once.
template<int D, int P>
__global__ void __launch_bounds__(256)
scatter_passes(const float* __restrict__ feat,
               const int* __restrict__ src,
               const int* __restrict__ dst,
               float* __restrict__ agg,
               float* __restrict__ cnt, int nE, int nSrc) {
    const int nbp  = gridDim.x / P;                 // blocks per pass
    const int pass = blockIdx.x / nbp;
    const int base = (blockIdx.x % nbp) * 64;       // 64 edges per block
    const int wid  = threadIdx.x >> 5;
    const int lane = threadIdx.x & 31;
    const int e    = base + wid * 8 + lane;         // lanes 0..7 carry edges

    const int lo = (int)(((long long)pass * nSrc) / P);
    const int hi = (int)(((long long)(pass + 1) * nSrc) / P);

    int s = 0, d = 0;
    bool in = false;
    if (lane < 8 && e < nE) {
        s = __ldg(src + e);
        in = (s >= lo) & (s < hi);
        if (in) d = __ldg(dst + e);
    }
    unsigned mask = __ballot_sync(0xffffffffu, in);
    while (mask) {
        int j = __ffs(mask) - 1;
        mask &= mask - 1;
        int ss = __shfl_sync(0xffffffffu, s, j);
        int dd = __shfl_sync(0xffffffffu, d, j);
        const float4* fs = (const float4*)(feat + (size_t)ss * D);
        float* ag = agg + (size_t)dd * D;
        #pragma unroll
        for (int k = 0; k < D / 128; k++) {
            float4 v = fs[k * 32 + lane];
            red_add_v4(ag + (size_t)(k * 32 + lane) * 4, v);
        }
        if (lane == 0) atomicAdd(&cnt[dd], 1.0f);
    }
}

// split fp32 -> bf16 hi/lo. First Kagg cols come from agg (scaled by 1/max(cnt,1)),
// next Kx cols from xsrc. Output row stride Kt.
__global__ void mean_split(const float* __restrict__ agg, const float* __restrict__ cnt,
                           const float* __restrict__ xsrc,
                           __nv_bfloat16* __restrict__ hi, __nv_bfloat16* __restrict__ lo,
                           int rows, int Kagg, int Kx, int Kt) {
    int Ks = Kagg + Kx;
    int i = blockIdx.x * blockDim.x + threadIdx.x;
    int tot = rows * (Ks / 4);
    if (i >= tot) return;
    int row = i / (Ks / 4);
    int c4 = (i % (Ks / 4)) * 4;
    float4 v;
    if (c4 < Kagg) {
        v = *(const float4*)(agg + (size_t)row * Kagg + c4);
        float inv = 1.0f / fmaxf(cnt[row], 1.0f);
        v.x *= inv; v.y *= inv; v.z *= inv; v.w *= inv;
    } else {
        v = *(const float4*)(xsrc + (size_t)row * Kx + (c4 - Kagg));
    }
    float f[4] = {v.x, v.y, v.z, v.w};
    alignas(8) __nv_bfloat16 h[4];
    alignas(8) __nv_bfloat16 l[4];
    #pragma unroll
    for (int j = 0; j < 4; j++) {
        h[j] = __float2bfloat16(f[j]);
        l[j] = __float2bfloat16(f[j] - __bfloat162float(h[j]));
    }
    *(uint2*)(hi + (size_t)row * Kt + c4) = *(uint2*)h;
    *(uint2*)(lo + (size_t)row * Kt + c4) = *(uint2*)l;
}

// concat two fp32 sources along K and split into bf16 hi/lo (for weights)
__global__ void split_cat(const float* __restrict__ s0, const float* __restrict__ s1,
                          __nv_bfloat16* __restrict__ hi, __nv_bfloat16* __restrict__ lo,
                          int rows, int K0, int K1) {
    int Kt = K0 + K1;
    int i = blockIdx.x * blockDim.x + threadIdx.x;
    int tot = rows * (Kt / 4);
    if (i >= tot) return;
    int row = i / (Kt / 4);
    int c4 = (i % (Kt / 4)) * 4;
    float4 v = (c4 < K0) ? *(const float4*)(s0 + (size_t)row * K0 + c4)
                         : *(const float4*)(s1 + (size_t)row * K1 + (c4 - K0));
    float f[4] = {v.x, v.y, v.z, v.w};
    alignas(8) __nv_bfloat16 h[4];
    alignas(8) __nv_bfloat16 l[4];
    #pragma unroll
    for (int j = 0; j < 4; j++) {
        h[j] = __float2bfloat16(f[j]);
        l[j] = __float2bfloat16(f[j] - __bfloat162float(h[j]));
    }
    *(uint2*)(hi + (size_t)row * Kt + c4) = *(uint2*)h;
    *(uint2*)(lo + (size_t)row * Kt + c4) = *(uint2*)l;
}

// ---------------- mma.sync bf16 GEMM (3-stage cp.async pipeline) ----------------
template<int BN, int K, bool RELU, bool WSPLIT>
__global__ void __launch_bounds__(256, 1)
gemm_mma(const __nv_bfloat16* __restrict__ Ah, const __nv_bfloat16* __restrict__ Al,
         const __nv_bfloat16* __restrict__ Bh, const __nv_bfloat16* __restrict__ Bl,
         const float* __restrict__ bias, float* __restrict__ C, int M,
         __nv_bfloat16* __restrict__ A2h, __nv_bfloat16* __restrict__ A2l, int n2) {
    constexpr int STAGES = 3;
    constexpr int KC = 64;
    constexpr int NCP = K / KC;
    constexpr int NCHUNK = 3 * NCP;
    constexpr int ATILE = 128 * 128;
    constexpr int BTILE = BN * 128;
    constexpr int STILE = ATILE + BTILE;
    constexpr int WN = BN / 4;
    constexpr int MT = 4;
    constexpr int NT = WN / 8;
    constexpr int NG = (1024 + BN * 8) / 256;

    extern __shared__ char dsm[];
    char* tb = (char*)((((uintptr_t)dsm) + 1023) & ~(uintptr_t)1023);
    uint32_t aBase[STAGES], bBase[STAGES];
    #pragma unroll
    for (int s = 0; s < STAGES; s++) {
        aBase[s] = smem_u32(tb + s * STILE);
        bBase[s] = smem_u32(tb + s * STILE + ATILE);
    }

    const int tid  = threadIdx.x;
    const int wid  = tid >> 5;
    const int lane = tid & 31;
    const int m0   = blockIdx.x * 128;
    const int wm0  = (wid >> 2) * 64;
    const int wn0  = (wid & 3) * WN;

    float acc[MT][NT][4];
    #pragma unroll
    for (int i = 0; i < MT; i++)
        #pragma unroll
        for (int j = 0; j < NT; j++)
            #pragma unroll
            for (int e = 0; e < 4; e++) acc[i][j][e] = 0.f;

    auto load_chunk = [&](int ch, int buf) {
        const int pass = ch / NCP;
        const int kc = (ch % NCP) * KC;
        const __nv_bfloat16* As = (pass < 2) ? Ah : Al;
        const __nv_bfloat16* Bs = (pass == 1) ? Bl : Bh;
        #pragma unroll
        for (int it = 0; it < NG; it++) {
            int g = tid + it * 256;
            if (g < 1024) {
                int row = g >> 3, c = g & 7;
                int gr = m0 + row;
                bool ok = gr < M;
                int grs = ok ? gr : (M - 1);
                cp16(aBase[buf] + sw128((uint32_t)(row * 128 + c * 16)),
                     As + (size_t)grs * K + kc + c * 8, ok);
            } else {
                int g2 = g - 1024;
                int row = g2 >> 3, c = g2 & 7;
                cp16(bBase[buf] + sw128((uint32_t)(row * 128 + c * 16)),
                     Bs + (size_t)row * K + kc + c * 8, true);
            }
        }
        asm volatile("cp.async.commit_group;" ::: "memory");
    };

    #pragma unroll
    for (int s = 0; s < STAGES - 1; s++) load_chunk(s, s);

    for (int ch = 0; ch < NCHUNK; ch++) {
        const int buf = ch % STAGES;
        if (ch == NCHUNK - 1)
            asm volatile("cp.async.wait_group 0;" ::: "memory");
        else
            asm volatile("cp.async.wait_group %0;" :: "n"(STAGES - 2) : "memory");
        __syncthreads();
        int nx = ch + STAGES - 1;
        if (nx < NCHUNK) load_chunk(nx, nx % STAGES);

        const uint32_t aB = aBase[buf];
        const uint32_t bB = bBase[buf];
        #pragma unroll
        for (int ks = 0; ks < 4; ks++) {
            const int kb = ks * 32;
            uint32_t bf[NT][2];
            #pragma unroll
            for (int nt2 = 0; nt2 < NT / 2; nt2++) {
                int n0 = wn0 + nt2 * 16;
                int rsel = (lane & 7) + ((lane >> 4) << 3);
                int ksel = (lane >> 3) & 1;
                uint32_t off = (uint32_t)((n0 + rsel) * 128 + kb + ksel * 16);
                ldsm4(bf[2 * nt2][0], bf[2 * nt2][1],
                      bf[2 * nt2 + 1][0], bf[2 * nt2 + 1][1], bB + sw128(off));
            }
            #pragma unroll
            for (int mt = 0; mt < MT; mt++) {
                int mrow = wm0 + mt * 16;
                int rsel = (lane & 7) + (((lane >> 3) & 1) << 3);
                int ksel = lane >> 4;
                uint32_t off = (uint32_t)((mrow + rsel) * 128 + kb + ksel * 16);
                uint32_t a0, a1, a2, a3;
                ldsm4(a0, a1, a2, a3, aB + sw128(off));
                #pragma unroll
                for (int nt = 0; nt < NT; nt++)
                    mma16816(acc[mt][nt], a0, a1, a2, a3, bf[nt][0], bf[nt][1]);
            }
        }
    }

    // epilogue
    #pragma unroll
    for (int mt = 0; mt < MT; mt++) {
        int rr[2];
        rr[0] = m0 + wm0 + mt * 16 + (lane >> 2);
        rr[1] = rr[0] + 8;
        #pragma unroll
        for (int nt = 0; nt < NT; nt++) {
            int c = wn0 + nt * 8 + (lane & 3) * 2;
            float2 bv = *(const float2*)(bias + c);
            #pragma unroll
            for (int half = 0; half < 2; half++) {
                int r = rr[half];
                if (r < M) {
                    float2 v = make_float2(acc[mt][nt][2 * half + 0] + bv.x,
                                           acc[mt][nt][2 * half + 1] + bv.y);
                    if (RELU) { v.x = fmaxf(v.x, 0.f); v.y = fmaxf(v.y, 0.f); }
                    *(float2*)(C + (size_t)r * BN + c) = v;
                    if (WSPLIT && r < n2) {
                        float hx = __bfloat162float(__float2bfloat16(v.x));
                        float hy = __bfloat162float(__float2bfloat16(v.y));
                        size_t o = (size_t)r * 512 + 256 + c;
                        *(uint32_t*)(A2h + o) = pack_bf16x2(hx, hy);
                        *(uint32_t*)(A2l + o) = pack_bf16x2(v.x - hx, v.y - hy);
                    }
                }
            }
        }
    }
}

// ---------------- host side ----------------
extern "C" void kernel_launch(void* const* d_in, const int* in_sizes, int n_in,
                              void* d_out, int out_size) {
    const float* x   = (const float*)d_in[0];
    const float* Wl0 = (const float*)d_in[1];
    const float* bl0 = (const float*)d_in[2];
    const float* Wr0 = (const float*)d_in[3];
    const float* Wl1 = (const float*)d_in[4];
    const float* bl1 = (const float*)d_in[5];
    const float* Wr1 = (const float*)d_in[6];
    const int* e0s = (const int*)d_in[7];
    const int* e0d = (const int*)d_in[8];
    const int* e1s = (const int*)d_in[9];
    const int* e1d = (const int*)d_in[10];
    float* out = (float*)d_out;

    float *agg0, *cnt0, *h, *agg1, *cnt1;
    __nv_bfloat16 *A1h, *A1l, *A2h, *A2l, *B1h, *B1l, *B2h, *B2l;
    cudaGetSymbolAddress((void**)&agg0, g_agg0);
    cudaGetSymbolAddress((void**)&cnt0, g_cnt0);
    cudaGetSymbolAddress((void**)&h,    g_h);
    cudaGetSymbolAddress((void**)&agg1, g_agg1);
    cudaGetSymbolAddress((void**)&cnt1, g_cnt1);
    cudaGetSymbolAddress((void**)&A1h, g_A1h);
    cudaGetSymbolAddress((void**)&A1l, g_A1l);
    cudaGetSymbolAddress((void**)&A2h, g_A2h);
    cudaGetSymbolAddress((void**)&A2l, g_A2l);
    cudaGetSymbolAddress((void**)&B1h, g_B1h);
    cudaGetSymbolAddress((void**)&B1l, g_B1l);
    cudaGetSymbolAddress((void**)&B2h, g_B2h);
    cudaGetSymbolAddress((void**)&B2l, g_B2l);

    const int smem1 = 1024 + 3 * (128 * 128 + 256 * 128);  // 148480
    const int smem2 = 1024 + 3 * (128 * 128 + 128 * 128);  // 99328
    cudaFuncSetAttribute(gemm_mma<256, 256, true, true>,
                         cudaFuncAttributeMaxDynamicSharedMemorySize, smem1);
    cudaFuncSetAttribute(gemm_mma<128, 512, false, false>,
                         cudaFuncAttributeMaxDynamicSharedMemorySize, smem2);

    // L0: zero accumulators
    {
        int tot = N1_ * D_IN_ / 4 + N1_ / 4 + N2_ * D_H_ / 4 + N2_ / 4;
        zero_all<<<(tot + 255) / 256, 256>>>((float4*)agg0, (float4*)cnt0,
                                             (float4*)agg1, (float4*)cnt1);
    }
    // L1, L2: weight splits
    {
        int t = 256 * (256 / 4);
        split_cat<<<(t + 255) / 256, 256>>>(Wl0, Wr0, B1h, B1l, 256, 128, 128);
        t = 128 * (512 / 4);
        split_cat<<<(t + 255) / 256, 256>>>(Wl1, Wr1, B2h, B2l, 128, 256, 256);
    }
    // L3: hop-0 scatter, 6 src-range passes (x window 43 MB -> L2-resident)
    {
        const int P = 6;
        int nbp = (E0_ + 63) / 64;
        scatter_passes<D_IN_, P><<<nbp * P, 256>>>(x, e0s, e0d, agg0, cnt0, E0_, N0_);
    }
    // L4: A1 = [mean(agg0) | x[:N1]] -> bf16 hi/lo (mean fused)
    {
        int t = N1_ * (256 / 4);
        mean_split<<<(t + 255) / 256, 256>>>(agg0, cnt0, x, A1h, A1l, N1_, 128, 128, 256);
    }
    // L5: h = relu(A1 @ B1^T + bl0); also emits A2 right half (h[:N2]) hi/lo
    {
        dim3 grid((N1_ + 127) / 128);
        gemm_mma<256, 256, true, true><<<grid, 256, smem1>>>(
            A1h, A1l, B1h, B1l, bl0, h, N1_, A2h, A2l, N2_);
    }
    // L6: hop-1 scatter, 3 src-range passes (h window 33 MB)
    {
        const int P = 3;
        int nbp = (E1_ + 63) / 64;
        scatter_passes<D_H_, P><<<nbp * P, 256>>>(h, e1s, e1d, agg1, cnt1, E1_, N1_);
    }
    // L7: A2 left half = mean(agg1) -> bf16 hi/lo (row stride 512)
    {
        int t = N2_ * (256 / 4);
        mean_split<<<(t + 255) / 256, 256>>>(agg1, cnt1, (const float*)nullptr,
                                             A2h, A2l, N2_, 256, 0, 512);
    }
    // L8: out = A2 @ B2^T + bl1
    {
        dim3 grid((N2_ + 127) / 128);
        gemm_mma<128, 512, false, false><<<grid, 256, smem2>>>(
            A2h, A2l, B2h, B2l, bl1, out, N2_, (__nv_bfloat16*)nullptr,
            (__nv_bfloat16*)nullptr, 0);
    }
}

// round 7
// speedup vs baseline: 2.0643x; 1.4049x over previous
#include <cuda_runtime.h>
#include <cuda_bf16.h>
#include <cstdint>

#define N0_   500000
#define N1_   100000
#define N2_   25000
#define E0_   1600000
#define E1_   400000
#define D_IN_ 128
#define D_H_  256
#define D_OUT_ 128

// padded CSR layout: seg0 = dst-degrees of hop0 (N1, padded to 102400),
// seg1 = dst-degrees of hop1 (N2, padded to 25600). 125 blocks x 1024.
#define PAD0_ 102400
#define TOT_  128000
#define SBLK_ 125

// ---- scratch (allocation-free rule: __device__ globals) ----
__device__ float g_h[(size_t)N1_ * D_H_];
__device__ int g_deg[TOT_];
__device__ int g_scan[TOT_];
__device__ int g_bsum[SBLK_];
__device__ int g_bsum2[SBLK_];
__device__ int g_off[TOT_];
__device__ int g_wcur[TOT_];
__device__ int g_csr0[E0_];
__device__ int g_csr1[E1_];
// bf16 split operand buffers (hi/lo)
__device__ __align__(128) __nv_bfloat16 g_A1h[(size_t)N1_ * 256];
__device__ __align__(128) __nv_bfloat16 g_A1l[(size_t)N1_ * 256];
__device__ __align__(128) __nv_bfloat16 g_A2h[(size_t)N2_ * 512];
__device__ __align__(128) __nv_bfloat16 g_A2l[(size_t)N2_ * 512];
__device__ __align__(128) __nv_bfloat16 g_B1h[256 * 256];
__device__ __align__(128) __nv_bfloat16 g_B1l[256 * 256];
__device__ __align__(128) __nv_bfloat16 g_B2h[128 * 512];
__device__ __align__(128) __nv_bfloat16 g_B2l[128 * 512];

// ---------------- ptx helpers (compute_103-safe) ----------------
__device__ __forceinline__ uint32_t smem_u32(const void* p) {
    uint32_t a;
    asm("{ .reg .u64 t; cvta.to.shared.u64 t, %1; cvt.u32.u64 %0, t; }" : "=r"(a) : "l"(p));
    return a;
}
__device__ __forceinline__ uint32_t sw128(uint32_t off) {
    return off ^ ((off >> 3) & 0x70);
}
__device__ __forceinline__ void cp16(uint32_t dst, const void* src, bool pred) {
    int sz = pred ? 16 : 0;
    asm volatile("cp.async.cg.shared.global [%0], [%1], 16, %2;"
                 :: "r"(dst), "l"(src), "r"(sz) : "memory");
}
__device__ __forceinline__ void ldsm4(uint32_t& r0, uint32_t& r1, uint32_t& r2, uint32_t& r3,
                                      uint32_t addr) {
    asm volatile("ldmatrix.sync.aligned.m8n8.x4.shared.b16 {%0,%1,%2,%3}, [%4];"
                 : "=r"(r0), "=r"(r1), "=r"(r2), "=r"(r3) : "r"(addr));
}
__device__ __forceinline__ void mma16816(float* c, uint32_t a0, uint32_t a1, uint32_t a2,
                                         uint32_t a3, uint32_t b0, uint32_t b1) {
    asm volatile(
        "mma.sync.aligned.m16n8k16.row.col.f32.bf16.bf16.f32 "
        "{%0,%1,%2,%3}, {%4,%5,%6,%7}, {%8,%9}, {%0,%1,%2,%3};"
        : "+f"(c[0]), "+f"(c[1]), "+f"(c[2]), "+f"(c[3])
        : "r"(a0), "r"(a1), "r"(a2), "r"(a3), "r"(b0), "r"(b1));
}
__device__ __forceinline__ uint32_t pack_bf16x2(float a, float b) {
    __nv_bfloat162 p = __floats2bfloat162_rn(a, b);
    return *(uint32_t*)&p;
}
__device__ __forceinline__ void split_store(__nv_bfloat16* hi, __nv_bfloat16* lo,
                                            size_t o, float4 v) {
    float hx = __bfloat162float(__float2bfloat16(v.x));
    float hy = __bfloat162float(__float2bfloat16(v.y));
    float hz = __bfloat162float(__float2bfloat16(v.z));
    float hw = __bfloat162float(__float2bfloat16(v.w));
    uint2 ph = make_uint2(pack_bf16x2(hx, hy), pack_bf16x2(hz, hw));
    uint2 pl = make_uint2(pack_bf16x2(v.x - hx, v.y - hy),
                          pack_bf16x2(v.z - hz, v.w - hw));
    *(uint2*)(hi + o) = ph;
    *(uint2*)(lo + o) = pl;
}

// ---------------- CSR build kernels ----------------
__global__ void zero_deg(int4* deg) {
    int i = blockIdx.x * blockDim.x + threadIdx.x;   // TOT_/4 entries
    if (i < TOT_ / 4) deg[i] = make_int4(0, 0, 0, 0);
}

__global__ void hist_deg(const int* __restrict__ d0, const int* __restrict__ d1,
                         int* __restrict__ deg) {
    int i = blockIdx.x * blockDim.x + threadIdx.x;
    if (i < E0_) atomicAdd(&deg[d0[i]], 1);
    else if (i < E0_ + E1_) atomicAdd(&deg[PAD0_ + d1[i - E0_]], 1);
}

__global__ void __launch_bounds__(1024) scan_part(const int* __restrict__ deg,
                                                  int* __restrict__ scn,
                                                  int* __restrict__ bsum) {
    __shared__ int sm[1024];
    int t = threadIdx.x;
    int gid = blockIdx.x * 1024 + t;
    sm[t] = deg[gid];
    __syncthreads();
    #pragma unroll
    for (int o = 1; o < 1024; o <<= 1) {
        int u = (t >= o) ? sm[t - o] : 0;
        __syncthreads();
        sm[t] += u;
        __syncthreads();
    }
    scn[gid] = sm[t];
    if (t == 1023) bsum[blockIdx.x] = sm[t];
}

__global__ void __launch_bounds__(128) scan_top(const int* __restrict__ bsum,
                                                int* __restrict__ bsum2) {
    __shared__ int sm[128];
    int t = threadIdx.x;
    sm[t] = (t < SBLK_) ? bsum[t] : 0;
    __syncthreads();
    #pragma unroll
    for (int o = 1; o < 128; o <<= 1) {
        int u = (t >= o) ? sm[t - o] : 0;
        __syncthreads();
        sm[t] += u;
        __syncthreads();
    }
    if (t < SBLK_) bsum2[t] = sm[t];
}

__global__ void scan_add(const int* __restrict__ scn, const int* __restrict__ deg,
                         const int* __restrict__ bsum2,
                         int* __restrict__ off, int* __restrict__ wcur) {
    int gid = blockIdx.x * blockDim.x + threadIdx.x;
    if (gid >= TOT_) return;
    int b = gid >> 10;
    int incl = scn[gid] + (b > 0 ? bsum2[b - 1] : 0);
    int start = incl - deg[gid];
    if (gid >= PAD0_) start -= E0_;
    off[gid] = start;
    wcur[gid] = start;
}

__global__ void fill_csr(const int* __restrict__ s0, const int* __restrict__ d0,
                         const int* __restrict__ s1, const int* __restrict__ d1,
                         int* __restrict__ wcur,
                         int* __restrict__ csr0, int* __restrict__ csr1) {
    int i = blockIdx.x * blockDim.x + threadIdx.x;
    if (i < E0_) {
        int pos = atomicAdd(&wcur[d0[i]], 1);
        csr0[pos] = s0[i];
    } else if (i < E0_ + E1_) {
        int j = i - E0_;
        int pos = atomicAdd(&wcur[PAD0_ + d1[j]], 1);
        csr1[pos] = s1[j];
    }
}

// ---------------- atomic-free gather + mean + bf16 split ----------------
// hop 0: warp per dst node; left half (cols 0..127) = mean of x[neigh],
// right half (cols 128..255) = x[row]. Writes A1 hi/lo, row stride 256.
__global__ void __launch_bounds__(256) gather0(const float* __restrict__ x,
                                               const int* __restrict__ off,
                                               const int* __restrict__ csr,
                                               __nv_bfloat16* __restrict__ hi,
                                               __nv_bfloat16* __restrict__ lo) {
    int row = (blockIdx.x * blockDim.x + threadIdx.x) >> 5;
    int lane = threadIdx.x & 31;
    if (row >= N1_) return;
    int start = off[row];
    int deg = off[row + 1] - start;

    float4 acc = make_float4(0.f, 0.f, 0.f, 0.f);
    for (int base = 0; base < deg; base += 32) {
        int idx = 0;
        if (base + lane < deg) idx = __ldg(csr + start + base + lane);
        int nn = min(32, deg - base);
        #pragma unroll 4
        for (int j = 0; j < nn; j++) {
            int s = __shfl_sync(0xffffffffu, idx, j);
            float4 v = __ldg((const float4*)(x + (size_t)s * D_IN_) + lane);
            acc.x += v.x; acc.y += v.y; acc.z += v.z; acc.w += v.w;
        }
    }
    float inv = 1.0f / fmaxf((float)deg, 1.0f);
    acc.x *= inv; acc.y *= inv; acc.z *= inv; acc.w *= inv;
    size_t ro = (size_t)row * 256 + lane * 4;
    split_store(hi, lo, ro, acc);
    float4 xr = __ldg((const float4*)(x + (size_t)row * D_IN_) + lane);
    split_store(hi, lo, ro + 128, xr);
}

// hop 1: warp per dst node over h (D=256); writes A2 left half (cols 0..255),
// row stride 512. Right half is produced by gemm1's epilogue.
__global__ void __launch_bounds__(256) gather1(const float* __restrict__ h,
                                               const int* __restrict__ off,
                                               const int* __restrict__ csr,
                                               __nv_bfloat16* __restrict__ hi,
                                               __nv_bfloat16* __restrict__ lo) {
    int row = (blockIdx.x * blockDim.x + threadIdx.x) >> 5;
    int lane = threadIdx.x & 31;
    if (row >= N2_) return;
    int start = off[PAD0_ + row];
    int deg = off[PAD0_ + row + 1] - start;

    float4 a0 = make_float4(0.f, 0.f, 0.f, 0.f);
    float4 a1 = make_float4(0.f, 0.f, 0.f, 0.f);
    for (int base = 0; base < deg; base += 32) {
        int idx = 0;
        if (base + lane < deg) idx = __ldg(csr + start + base + lane);
        int nn = min(32, deg - base);
        #pragma unroll 2
        for (int j = 0; j < nn; j++) {
            int s = __shfl_sync(0xffffffffu, idx, j);
            const float4* hr = (const float4*)(h + (size_t)s * D_H_);
            float4 v0 = __ldg(hr + lane);
            float4 v1 = __ldg(hr + 32 + lane);
            a0.x += v0.x; a0.y += v0.y; a0.z += v0.z; a0.w += v0.w;
            a1.x += v1.x; a1.y += v1.y; a1.z += v1.z; a1.w += v1.w;
        }
    }
    float inv = 1.0f / fmaxf((float)deg, 1.0f);
    a0.x *= inv; a0.y *= inv; a0.z *= inv; a0.w *= inv;
    a1.x *= inv; a1.y *= inv; a1.z *= inv; a1.w *= inv;
    size_t ro = (size_t)row * 512 + lane * 4;
    split_store(hi, lo, ro, a0);
    split_store(hi, lo, ro + 128, a1);
}

// concat two fp32 sources along K and split into bf16 hi/lo (for weights)
__global__ void split_cat(const float* __restrict__ s0, const float* __restrict__ s1,
                          __nv_bfloat16* __restrict__ hi, __nv_bfloat16* __restrict__ lo,
                          int rows, int K0, int K1) {
    int Kt = K0 + K1;
    int i = blockIdx.x * blockDim.x + threadIdx.x;
    int tot = rows * (Kt / 4);
    if (i >= tot) return;
    int row = i / (Kt / 4);
    int c4 = (i % (Kt / 4)) * 4;
    float4 v = (c4 < K0) ? *(const float4*)(s0 + (size_t)row * K0 + c4)
                         : *(const float4*)(s1 + (size_t)row * K1 + (c4 - K0));
    split_store(hi, lo, (size_t)row * Kt + c4, v);
}

// ---------------- mma.sync bf16 GEMM (3-stage cp.async pipeline) ----------------
template<int BN, int K, bool RELU, bool WSPLIT>
__global__ void __launch_bounds__(256, 1)
gemm_mma(const __nv_bfloat16* __restrict__ Ah, const __nv_bfloat16* __restrict__ Al,
         const __nv_bfloat16* __restrict__ Bh, const __nv_bfloat16* __restrict__ Bl,
         const float* __restrict__ bias, float* __restrict__ C, int M,
         __nv_bfloat16* __restrict__ A2h, __nv_bfloat16* __restrict__ A2l, int n2) {
    constexpr int STAGES = 3;
    constexpr int KC = 64;
    constexpr int NCP = K / KC;
    constexpr int NCHUNK = 3 * NCP;
    constexpr int ATILE = 128 * 128;
    constexpr int BTILE = BN * 128;
    constexpr int STILE = ATILE + BTILE;
    constexpr int WN = BN / 4;
    constexpr int MT = 4;
    constexpr int NT = WN / 8;
    constexpr int NG = (1024 + BN * 8) / 256;

    extern __shared__ char dsm[];
    char* tb = (char*)((((uintptr_t)dsm) + 1023) & ~(uintptr_t)1023);
    uint32_t aBase[STAGES], bBase[STAGES];
    #pragma unroll
    for (int s = 0; s < STAGES; s++) {
        aBase[s] = smem_u32(tb + s * STILE);
        bBase[s] = smem_u32(tb + s * STILE + ATILE);
    }

    const int tid  = threadIdx.x;
    const int wid  = tid >> 5;
    const int lane = tid & 31;
    const int m0   = blockIdx.x * 128;
    const int wm0  = (wid >> 2) * 64;
    const int wn0  = (wid & 3) * WN;

    float acc[MT][NT][4];
    #pragma unroll
    for (int i = 0; i < MT; i++)
        #pragma unroll
        for (int j = 0; j < NT; j++)
            #pragma unroll
            for (int e = 0; e < 4; e++) acc[i][j][e] = 0.f;

    auto load_chunk = [&](int ch, int buf) {
        const int pass = ch / NCP;
        const int kc = (ch % NCP) * KC;
        const __nv_bfloat16* As = (pass < 2) ? Ah : Al;
        const __nv_bfloat16* Bs = (pass == 1) ? Bl : Bh;
        #pragma unroll
        for (int it = 0; it < NG; it++) {
            int g = tid + it * 256;
            if (g < 1024) {
                int row = g >> 3, c = g & 7;
                int gr = m0 + row;
                bool ok = gr < M;
                int grs = ok ? gr : (M - 1);
                cp16(aBase[buf] + sw128((uint32_t)(row * 128 + c * 16)),
                     As + (size_t)grs * K + kc + c * 8, ok);
            } else {
                int g2 = g - 1024;
                int row = g2 >> 3, c = g2 & 7;
                cp16(bBase[buf] + sw128((uint32_t)(row * 128 + c * 16)),
                     Bs + (size_t)row * K + kc + c * 8, true);
            }
        }
        asm volatile("cp.async.commit_group;" ::: "memory");
    };

    #pragma unroll
    for (int s = 0; s < STAGES - 1; s++) load_chunk(s, s);

    for (int ch = 0; ch < NCHUNK; ch++) {
        const int buf = ch % STAGES;
        if (ch == NCHUNK - 1)
            asm volatile("cp.async.wait_group 0;" ::: "memory");
        else
            asm volatile("cp.async.wait_group %0;" :: "n"(STAGES - 2) : "memory");
        __syncthreads();
        int nx = ch + STAGES - 1;
        if (nx < NCHUNK) load_chunk(nx, nx % STAGES);

        const uint32_t aB = aBase[buf];
        const uint32_t bB = bBase[buf];
        #pragma unroll
        for (int ks = 0; ks < 4; ks++) {
            const int kb = ks * 32;
            uint32_t bf[NT][2];
            #pragma unroll
            for (int nt2 = 0; nt2 < NT / 2; nt2++) {
                int n0 = wn0 + nt2 * 16;
                int rsel = (lane & 7) + ((lane >> 4) << 3);
                int ksel = (lane >> 3) & 1;
                uint32_t off = (uint32_t)((n0 + rsel) * 128 + kb + ksel * 16);
                ldsm4(bf[2 * nt2][0], bf[2 * nt2][1],
                      bf[2 * nt2 + 1][0], bf[2 * nt2 + 1][1], bB + sw128(off));
            }
            #pragma unroll
            for (int mt = 0; mt < MT; mt++) {
                int mrow = wm0 + mt * 16;
                int rsel = (lane & 7) + (((lane >> 3) & 1) << 3);
                int ksel = lane >> 4;
                uint32_t off = (uint32_t)((mrow + rsel) * 128 + kb + ksel * 16);
                uint32_t a0, a1, a2, a3;
                ldsm4(a0, a1, a2, a3, aB + sw128(off));
                #pragma unroll
                for (int nt = 0; nt < NT; nt++)
                    mma16816(acc[mt][nt], a0, a1, a2, a3, bf[nt][0], bf[nt][1]);
            }
        }
    }

    // epilogue
    #pragma unroll
    for (int mt = 0; mt < MT; mt++) {
        int rr[2];
        rr[0] = m0 + wm0 + mt * 16 + (lane >> 2);
        rr[1] = rr[0] + 8;
        #pragma unroll
        for (int nt = 0; nt < NT; nt++) {
            int c = wn0 + nt * 8 + (lane & 3) * 2;
            float2 bv = *(const float2*)(bias + c);
            #pragma unroll
            for (int half = 0; half < 2; half++) {
                int r = rr[half];
                if (r < M) {
                    float2 v = make_float2(acc[mt][nt][2 * half + 0] + bv.x,
                                           acc[mt][nt][2 * half + 1] + bv.y);
                    if (RELU) { v.x = fmaxf(v.x, 0.f); v.y = fmaxf(v.y, 0.f); }
                    *(float2*)(C + (size_t)r * BN + c) = v;
                    if (WSPLIT && r < n2) {
                        float hx = __bfloat162float(__float2bfloat16(v.x));
                        float hy = __bfloat162float(__float2bfloat16(v.y));
                        size_t o = (size_t)r * 512 + 256 + c;
                        *(uint32_t*)(A2h + o) = pack_bf16x2(hx, hy);
                        *(uint32_t*)(A2l + o) = pack_bf16x2(v.x - hx, v.y - hy);
                    }
                }
            }
        }
    }
}

// ---------------- host side ----------------
extern "C" void kernel_launch(void* const* d_in, const int* in_sizes, int n_in,
                              void* d_out, int out_size) {
    const float* x   = (const float*)d_in[0];
    const float* Wl0 = (const float*)d_in[1];
    const float* bl0 = (const float*)d_in[2];
    const float* Wr0 = (const float*)d_in[3];
    const float* Wl1 = (const float*)d_in[4];
    const float* bl1 = (const float*)d_in[5];
    const float* Wr1 = (const float*)d_in[6];
    const int* e0s = (const int*)d_in[7];
    const int* e0d = (const int*)d_in[8];
    const int* e1s = (const int*)d_in[9];
    const int* e1d = (const int*)d_in[10];
    float* out = (float*)d_out;

    float* h;
    int *deg, *scn, *bsum, *bsum2, *off, *wcur, *csr0, *csr1;
    __nv_bfloat16 *A1h, *A1l, *A2h, *A2l, *B1h, *B1l, *B2h, *B2l;
    cudaGetSymbolAddress((void**)&h,    g_h);
    cudaGetSymbolAddress((void**)&deg,  g_deg);
    cudaGetSymbolAddress((void**)&scn,  g_scan);
    cudaGetSymbolAddress((void**)&bsum, g_bsum);
    cudaGetSymbolAddress((void**)&bsum2, g_bsum2);
    cudaGetSymbolAddress((void**)&off,  g_off);
    cudaGetSymbolAddress((void**)&wcur, g_wcur);
    cudaGetSymbolAddress((void**)&csr0, g_csr0);
    cudaGetSymbolAddress((void**)&csr1, g_csr1);
    cudaGetSymbolAddress((void**)&A1h, g_A1h);
    cudaGetSymbolAddress((void**)&A1l, g_A1l);
    cudaGetSymbolAddress((void**)&A2h, g_A2h);
    cudaGetSymbolAddress((void**)&A2l, g_A2l);
    cudaGetSymbolAddress((void**)&B1h, g_B1h);
    cudaGetSymbolAddress((void**)&B1l, g_B1l);
    cudaGetSymbolAddress((void**)&B2h, g_B2h);
    cudaGetSymbolAddress((void**)&B2l, g_B2l);

    const int smem1 = 1024 + 3 * (128 * 128 + 256 * 128);  // 148480
    const int smem2 = 1024 + 3 * (128 * 128 + 128 * 128);  // 99328
    cudaFuncSetAttribute(gemm_mma<256, 256, true, true>,
                         cudaFuncAttributeMaxDynamicSharedMemorySize, smem1);
    cudaFuncSetAttribute(gemm_mma<128, 512, false, false>,
                         cudaFuncAttributeMaxDynamicSharedMemorySize, smem2);

    const int ET = E0_ + E1_;

    // CSR build (both hops share kernels)
    zero_deg<<<(TOT_ / 4 + 255) / 256, 256>>>((int4*)deg);
    hist_deg<<<(ET + 255) / 256, 256>>>(e0d, e1d, deg);
    scan_part<<<SBLK_, 1024>>>(deg, scn, bsum);
    scan_top<<<1, 128>>>(bsum, bsum2);
    scan_add<<<(TOT_ + 255) / 256, 256>>>(scn, deg, bsum2, off, wcur);
    fill_csr<<<(ET + 255) / 256, 256>>>(e0s, e0d, e1s, e1d, wcur, csr0, csr1);

    // weight splits
    {
        int t = 256 * (256 / 4);
        split_cat<<<(t + 255) / 256, 256>>>(Wl0, Wr0, B1h, B1l, 256, 128, 128);
        t = 128 * (512 / 4);
        split_cat<<<(t + 255) / 256, 256>>>(Wl1, Wr1, B2h, B2l, 128, 256, 256);
    }

    // hop 0: gather + mean + split -> A1 (both halves)
    gather0<<<(N1_ * 32 + 255) / 256, 256>>>(x, off, csr0, A1h, A1l);

    // h = relu(A1 @ B1^T + bl0); epilogue also emits A2 right half (h[:N2])
    {
        dim3 grid((N1_ + 127) / 128);
        gemm_mma<256, 256, true, true><<<grid, 256, smem1>>>(
            A1h, A1l, B1h, B1l, bl0, h, N1_, A2h, A2l, N2_);
    }

    // hop 1: gather + mean + split -> A2 left half
    gather1<<<(N2_ * 32 + 255) / 256, 256>>>(h, off, csr1, A2h, A2l);

    // out = A2 @ B2^T + bl1
    {
        dim3 grid((N2_ + 127) / 128);
        gemm_mma<128, 512, false, false><<<grid, 256, smem2>>>(
            A2h, A2l, B2h, B2l, bl1, out, N2_, (__nv_bfloat16*)nullptr,
            (__nv_bfloat16*)nullptr, 0);
    }
}